// round 1
// baseline (speedup 1.0000x reference)
#include <cuda_runtime.h>

#define LSEQ 512
#define NH   8
#define DH   64
#define MD   512

// ---------------- scratch (device globals; no allocation allowed) ----------
__device__ float g_q[LSEQ * MD];      // layout [l, h*64+d], pre-scaled by 1/8
__device__ float g_k[LSEQ * MD];      // layout [m, h*64+d]
__device__ float g_v[LSEQ * MD];      // layout [m, h*64+d]
__device__ float g_attn[NH * LSEQ * LSEQ];   // [h, l, m]
__device__ float g_ctx[LSEQ * MD];    // [l, h*64+d]

// ---------------- generic 512x512x512 tiled GEMM tile (64x64 per block) ----
// C = (A @ B + bias) * scale    A:[512,512] row-major, B:[512,512] row-major
__device__ __forceinline__ void gemm_tile_512(const float* __restrict__ A,
                                              const float* __restrict__ B,
                                              const float* __restrict__ bias,
                                              float* __restrict__ C,
                                              float scale) {
    __shared__ float As[16][64];
    __shared__ float Bs[16][68];   // pad to 68 to de-conflict; rows stay 16B-aligned
    const int tid = threadIdx.x;
    const int bm = blockIdx.y * 64;
    const int bn = blockIdx.x * 64;
    const int tr = (tid / 16) * 4;
    const int tc = (tid % 16) * 4;

    float acc[4][4] = {};

    const int am = tid >> 2;            // 0..63 : A row within tile
    const int ak = (tid & 3) * 4;       // 0..12 : A k quad
    const int bk = tid >> 4;            // 0..15 : B k row
    const int bn4 = (tid & 15) * 4;     // 0..60 : B col quad

    for (int k0 = 0; k0 < 512; k0 += 16) {
        float4 a = *(const float4*)(A + (bm + am) * 512 + k0 + ak);
        As[ak + 0][am] = a.x;
        As[ak + 1][am] = a.y;
        As[ak + 2][am] = a.z;
        As[ak + 3][am] = a.w;
        float4 b = *(const float4*)(B + (k0 + bk) * 512 + bn + bn4);
        *(float4*)&Bs[bk][bn4] = b;
        __syncthreads();
#pragma unroll
        for (int kk = 0; kk < 16; kk++) {
            float ra[4], rb[4];
#pragma unroll
            for (int i = 0; i < 4; i++) ra[i] = As[kk][tr + i];
#pragma unroll
            for (int j = 0; j < 4; j++) rb[j] = Bs[kk][tc + j];
#pragma unroll
            for (int i = 0; i < 4; i++)
#pragma unroll
                for (int j = 0; j < 4; j++) acc[i][j] += ra[i] * rb[j];
        }
        __syncthreads();
    }
#pragma unroll
    for (int i = 0; i < 4; i++) {
        int row = bm + tr + i;
#pragma unroll
        for (int j = 0; j < 4; j++) {
            int col = bn + tc + j;
            C[row * 512 + col] = (acc[i][j] + bias[col]) * scale;
        }
    }
}

// ---------------- kernel 1: q/k/v projections (grid.z selects) -------------
__global__ void __launch_bounds__(256) proj_kernel(
    const float* __restrict__ q_in, const float* __restrict__ k_in,
    const float* __restrict__ v_in,
    const float* __restrict__ Wq, const float* __restrict__ bq,
    const float* __restrict__ Wk, const float* __restrict__ bk,
    const float* __restrict__ Wv, const float* __restrict__ bv) {
    if (blockIdx.z == 0) {
        gemm_tile_512(q_in, Wq, bq, g_q, 0.125f);   // 1/sqrt(64)
    } else if (blockIdx.z == 1) {
        gemm_tile_512(k_in, Wk, bk, g_k, 1.0f);
    } else {
        gemm_tile_512(v_in, Wv, bv, g_v, 1.0f);
    }
}

// ---------------- kernel 2: logits (qk + q.rel_k) fused with softmax -------
// one block per (l, h); 256 threads = 8 warps; warp w handles m in [w*64, w*64+64)
__global__ void __launch_bounds__(256) logits_softmax_kernel(
    const float* __restrict__ rel_k, float* __restrict__ attn_out) {
    const int l = blockIdx.x;
    const int h = blockIdx.y;
    const int tid = threadIdx.x;
    const int lane = tid & 31;
    const int warp = tid >> 5;

    __shared__ float s_logits[512];
    __shared__ float s_red[8];
    __shared__ float s_red2[8];

    // q fragment for this lane (2 consecutive d per lane)
    const float2 q2 = *(const float2*)(g_q + l * 512 + h * 64 + lane * 2);
    const float* rk_base = rel_k + ((h * 512 + l) * 512) * 64;
    const float* k_base = g_k + h * 64;

    const int m_lo = warp * 64;
#pragma unroll 4
    for (int mi = 0; mi < 64; mi += 4) {
        const int m = m_lo + mi;
        float2 r0 = *(const float2*)(rk_base + (m + 0) * 64 + lane * 2);
        float2 r1 = *(const float2*)(rk_base + (m + 1) * 64 + lane * 2);
        float2 r2 = *(const float2*)(rk_base + (m + 2) * 64 + lane * 2);
        float2 r3 = *(const float2*)(rk_base + (m + 3) * 64 + lane * 2);
        float2 k0 = *(const float2*)(k_base + (m + 0) * 512 + lane * 2);
        float2 k1 = *(const float2*)(k_base + (m + 1) * 512 + lane * 2);
        float2 k2 = *(const float2*)(k_base + (m + 2) * 512 + lane * 2);
        float2 k3 = *(const float2*)(k_base + (m + 3) * 512 + lane * 2);
        float s0 = q2.x * (r0.x + k0.x) + q2.y * (r0.y + k0.y);
        float s1 = q2.x * (r1.x + k1.x) + q2.y * (r1.y + k1.y);
        float s2 = q2.x * (r2.x + k2.x) + q2.y * (r2.y + k2.y);
        float s3 = q2.x * (r3.x + k3.x) + q2.y * (r3.y + k3.y);
#pragma unroll
        for (int o = 16; o > 0; o >>= 1) {
            s0 += __shfl_xor_sync(0xffffffffu, s0, o);
            s1 += __shfl_xor_sync(0xffffffffu, s1, o);
            s2 += __shfl_xor_sync(0xffffffffu, s2, o);
            s3 += __shfl_xor_sync(0xffffffffu, s3, o);
        }
        if (lane == 0) {
            s_logits[m + 0] = s0;
            s_logits[m + 1] = s1;
            s_logits[m + 2] = s2;
            s_logits[m + 3] = s3;
        }
    }
    __syncthreads();

    // ---- block softmax over 512 ----
    float v0 = s_logits[tid];
    float v1 = s_logits[tid + 256];
    float mx = fmaxf(v0, v1);
#pragma unroll
    for (int o = 16; o > 0; o >>= 1) mx = fmaxf(mx, __shfl_xor_sync(0xffffffffu, mx, o));
    if (lane == 0) s_red[warp] = mx;
    __syncthreads();
    float bmx = s_red[0];
#pragma unroll
    for (int i = 1; i < 8; i++) bmx = fmaxf(bmx, s_red[i]);

    float e0 = __expf(v0 - bmx);
    float e1 = __expf(v1 - bmx);
    float sm = e0 + e1;
#pragma unroll
    for (int o = 16; o > 0; o >>= 1) sm += __shfl_xor_sync(0xffffffffu, sm, o);
    if (lane == 0) s_red2[warp] = sm;
    __syncthreads();
    float bsum = s_red2[0];
#pragma unroll
    for (int i = 1; i < 8; i++) bsum += s_red2[i];
    const float inv = 1.0f / bsum;

    const float a0 = e0 * inv;
    const float a1 = e1 * inv;
    float* arow = g_attn + (h * 512 + l) * 512;
    arow[tid] = a0;
    arow[tid + 256] = a1;
    if (attn_out) {
        float* orow = attn_out + (h * 512 + l) * 512;
        orow[tid] = a0;
        orow[tid + 256] = a1;
    }
}

// ---------------- kernel 3: context = attn @ (v + rel_v) -------------------
// one block per (l, h); thread = (m-group 0..3, d 0..63)
__global__ void __launch_bounds__(256) context_kernel(const float* __restrict__ rel_v) {
    const int l = blockIdx.x;
    const int h = blockIdx.y;
    const int tid = threadIdx.x;
    const int d = tid & 63;
    const int mg = tid >> 6;   // 0..3

    __shared__ float s_a[512];
    __shared__ float s_p[256];

    const float* arow = g_attn + (h * 512 + l) * 512;
    s_a[tid] = arow[tid];
    s_a[tid + 256] = arow[tid + 256];
    __syncthreads();

    const float* rv_base = rel_v + ((h * 512 + l) * 512) * 64;
    const float* v_base = g_v + h * 64;

    float acc = 0.0f;
#pragma unroll 4
    for (int m = mg; m < 512; m += 8) {
        const float a0 = s_a[m];
        const float a1 = s_a[m + 4];
        const float rv0 = rv_base[m * 64 + d];
        const float rv1 = rv_base[(m + 4) * 64 + d];
        const float vv0 = v_base[m * 512 + d];
        const float vv1 = v_base[(m + 4) * 512 + d];
        acc += a0 * (rv0 + vv0) + a1 * (rv1 + vv1);
    }
    s_p[tid] = acc;
    __syncthreads();
    if (tid < 64) {
        float r = s_p[tid] + s_p[tid + 64] + s_p[tid + 128] + s_p[tid + 192];
        g_ctx[l * 512 + h * 64 + tid] = r;
    }
}

// ---------------- kernel 4: output = ctx @ Wo + bo -------------------------
__global__ void __launch_bounds__(256) out_proj_kernel(
    const float* __restrict__ Wo, const float* __restrict__ bo,
    float* __restrict__ out) {
    gemm_tile_512(g_ctx, Wo, bo, out, 1.0f);
}

// ---------------- launch ---------------------------------------------------
extern "C" void kernel_launch(void* const* d_in, const int* in_sizes, int n_in,
                              void* d_out, int out_size) {
    const float* query = (const float*)d_in[0];
    const float* key   = (const float*)d_in[1];
    const float* value = (const float*)d_in[2];
    const float* rel_k = (const float*)d_in[3];
    const float* rel_v = (const float*)d_in[4];
    const float* Wq = (const float*)d_in[5];
    const float* bq = (const float*)d_in[6];
    const float* Wk = (const float*)d_in[7];
    const float* bk = (const float*)d_in[8];
    const float* Wv = (const float*)d_in[9];
    const float* bv = (const float*)d_in[10];
    const float* Wo = (const float*)d_in[11];
    const float* bo = (const float*)d_in[12];

    float* out = (float*)d_out;
    float* attn_out = nullptr;
    const int OUT_ELEMS = 512 * 512;
    const int ATTN_ELEMS = 8 * 512 * 512;
    if (out_size >= OUT_ELEMS + ATTN_ELEMS) attn_out = out + OUT_ELEMS;

    dim3 proj_grid(8, 8, 3);
    proj_kernel<<<proj_grid, 256>>>(query, key, value, Wq, bq, Wk, bk, Wv, bv);

    dim3 lg(512, 8);
    logits_softmax_kernel<<<lg, 256>>>(rel_k, attn_out);
    context_kernel<<<lg, 256>>>(rel_v);

    dim3 og(8, 8);
    out_proj_kernel<<<og, 256>>>(Wo, bo, out);
}

// round 2
// speedup vs baseline: 1.0707x; 1.0707x over previous
#include <cuda_runtime.h>

#define LSEQ 512
#define NH   8
#define DH   64
#define MD   512

// ---------------- scratch (device globals; no allocation allowed) ----------
__device__ float g_q[LSEQ * MD];                 // [l, h*64+d], pre-scaled 1/8
__device__ float g_k[LSEQ * MD];                 // [m, h*64+d]
__device__ float g_v[LSEQ * MD];                 // [m, h*64+d]
__device__ float g_logits[NH * LSEQ * LSEQ];     // [h, l, m] : q k^T part
__device__ float g_attn[NH * LSEQ * LSEQ];       // [h, l, m]
__device__ float g_ctx[LSEQ * MD];               // [l, h*64+d]

// ---------------- 64x64 GEMM tile core (vector LDS inner loop) -------------
// C = (A @ B + bias) * scale, A/B/C 512-stride row-major, full K=512
__device__ __forceinline__ void gemm_tile_512(const float* __restrict__ A,
                                              const float* __restrict__ B,
                                              const float* __restrict__ bias,
                                              float* __restrict__ C,
                                              float scale) {
    __shared__ float As[16][64];
    __shared__ float Bs[16][68];
    const int tid = threadIdx.x;
    const int bm = blockIdx.y * 64;
    const int bn = blockIdx.x * 64;
    const int tr = (tid / 16) * 4;
    const int tc = (tid % 16) * 4;
    float acc[4][4] = {};

    const int am = tid >> 2;
    const int ak = (tid & 3) * 4;
    const int bk = tid >> 4;
    const int bn4 = (tid & 15) * 4;

    for (int k0 = 0; k0 < 512; k0 += 16) {
        float4 a = *(const float4*)(A + (bm + am) * 512 + k0 + ak);
        As[ak + 0][am] = a.x; As[ak + 1][am] = a.y;
        As[ak + 2][am] = a.z; As[ak + 3][am] = a.w;
        *(float4*)&Bs[bk][bn4] = *(const float4*)(B + (k0 + bk) * 512 + bn + bn4);
        __syncthreads();
#pragma unroll
        for (int kk = 0; kk < 16; kk++) {
            float4 ra = *(const float4*)&As[kk][tr];
            float4 rb = *(const float4*)&Bs[kk][tc];
            acc[0][0] += ra.x * rb.x; acc[0][1] += ra.x * rb.y;
            acc[0][2] += ra.x * rb.z; acc[0][3] += ra.x * rb.w;
            acc[1][0] += ra.y * rb.x; acc[1][1] += ra.y * rb.y;
            acc[1][2] += ra.y * rb.z; acc[1][3] += ra.y * rb.w;
            acc[2][0] += ra.z * rb.x; acc[2][1] += ra.z * rb.y;
            acc[2][2] += ra.z * rb.z; acc[2][3] += ra.z * rb.w;
            acc[3][0] += ra.w * rb.x; acc[3][1] += ra.w * rb.y;
            acc[3][2] += ra.w * rb.z; acc[3][3] += ra.w * rb.w;
        }
        __syncthreads();
    }
#pragma unroll
    for (int i = 0; i < 4; i++) {
        int row = bm + tr + i;
#pragma unroll
        for (int j = 0; j < 4; j++) {
            int col = bn + tc + j;
            C[row * 512 + col] = (acc[i][j] + bias[col]) * scale;
        }
    }
}

// ---------------- kernel 1: q/k/v projections ------------------------------
__global__ void __launch_bounds__(256) proj_kernel(
    const float* __restrict__ q_in, const float* __restrict__ k_in,
    const float* __restrict__ v_in,
    const float* __restrict__ Wq, const float* __restrict__ bq,
    const float* __restrict__ Wk, const float* __restrict__ bk,
    const float* __restrict__ Wv, const float* __restrict__ bv) {
    if (blockIdx.z == 0)      gemm_tile_512(q_in, Wq, bq, g_q, 0.125f);
    else if (blockIdx.z == 1) gemm_tile_512(k_in, Wk, bk, g_k, 1.0f);
    else                      gemm_tile_512(v_in, Wv, bv, g_v, 1.0f);
}

// ---------------- kernel 2: S = q @ k^T per head (K=64) --------------------
// grid (8 ntile, 8 mtile, 8 head)
__global__ void __launch_bounds__(256) qk_gemm_kernel() {
    __shared__ float As[16][64];
    __shared__ float Bs[16][68];
    const int tid = threadIdx.x;
    const int h = blockIdx.z;
    const int bm = blockIdx.y * 64;   // l tile
    const int bn = blockIdx.x * 64;   // m tile
    const int tr = (tid / 16) * 4;
    const int tc = (tid % 16) * 4;
    float acc[4][4] = {};

    const int r = tid >> 2;            // row within tile (both A and Bt)
    const int kq = (tid & 3) * 4;      // k quad 0..12

    const float* Ah = g_q + h * 64;
    const float* Bh = g_k + h * 64;

    for (int k0 = 0; k0 < 64; k0 += 16) {
        float4 a = *(const float4*)(Ah + (bm + r) * 512 + k0 + kq);
        As[kq + 0][r] = a.x; As[kq + 1][r] = a.y;
        As[kq + 2][r] = a.z; As[kq + 3][r] = a.w;
        float4 b = *(const float4*)(Bh + (bn + r) * 512 + k0 + kq);
        Bs[kq + 0][r] = b.x; Bs[kq + 1][r] = b.y;
        Bs[kq + 2][r] = b.z; Bs[kq + 3][r] = b.w;
        __syncthreads();
#pragma unroll
        for (int kk = 0; kk < 16; kk++) {
            float4 ra = *(const float4*)&As[kk][tr];
            float4 rb = *(const float4*)&Bs[kk][tc];
            acc[0][0] += ra.x * rb.x; acc[0][1] += ra.x * rb.y;
            acc[0][2] += ra.x * rb.z; acc[0][3] += ra.x * rb.w;
            acc[1][0] += ra.y * rb.x; acc[1][1] += ra.y * rb.y;
            acc[1][2] += ra.y * rb.z; acc[1][3] += ra.y * rb.w;
            acc[2][0] += ra.z * rb.x; acc[2][1] += ra.z * rb.y;
            acc[2][2] += ra.z * rb.z; acc[2][3] += ra.z * rb.w;
            acc[3][0] += ra.w * rb.x; acc[3][1] += ra.w * rb.y;
            acc[3][2] += ra.w * rb.z; acc[3][3] += ra.w * rb.w;
        }
        __syncthreads();
    }
    float* Crow = g_logits + (size_t)(h * 512) * 512;
#pragma unroll
    for (int i = 0; i < 4; i++)
#pragma unroll
        for (int j = 0; j < 4; j++)
            Crow[(bm + tr + i) * 512 + bn + tc + j] = acc[i][j];
}

// ---------------- kernel 3: rel logits + softmax ---------------------------
// one block per (l, h); 256 threads = 8 warps; warp w handles m in [w*64, ...)
__global__ void __launch_bounds__(256) logits_softmax_kernel(
    const float* __restrict__ rel_k, float* __restrict__ attn_out) {
    const int l = blockIdx.x;
    const int h = blockIdx.y;
    const int tid = threadIdx.x;
    const int lane = tid & 31;
    const int warp = tid >> 5;
    const int li = lane & 15;    // element-quad within row
    const int gg = lane >> 4;    // which of 2 m rows

    __shared__ float s_logits[512];
    __shared__ float s_red[8];
    __shared__ float s_red2[8];

    const float4 q4 = *(const float4*)(g_q + l * 512 + h * 64 + li * 4);
    const float* rk_base = rel_k + ((size_t)(h * 512 + l) * 512) * 64;

    const int m_lo = warp * 64;
#pragma unroll 8
    for (int mi = 0; mi < 64; mi += 2) {
        const int m = m_lo + mi + gg;
        float4 r = *(const float4*)(rk_base + (size_t)m * 64 + li * 4);
        float s = q4.x * r.x + q4.y * r.y + q4.z * r.z + q4.w * r.w;
#pragma unroll
        for (int o = 8; o > 0; o >>= 1) s += __shfl_xor_sync(0xffffffffu, s, o);
        if (li == 0) s_logits[m] = s;
    }
    __syncthreads();

    const float* Srow = g_logits + (size_t)(h * 512 + l) * 512;
    float v0 = s_logits[tid] + Srow[tid];
    float v1 = s_logits[tid + 256] + Srow[tid + 256];
    float mx = fmaxf(v0, v1);
#pragma unroll
    for (int o = 16; o > 0; o >>= 1) mx = fmaxf(mx, __shfl_xor_sync(0xffffffffu, mx, o));
    if (lane == 0) s_red[warp] = mx;
    __syncthreads();
    float bmx = s_red[0];
#pragma unroll
    for (int i = 1; i < 8; i++) bmx = fmaxf(bmx, s_red[i]);

    float e0 = __expf(v0 - bmx);
    float e1 = __expf(v1 - bmx);
    float sm = e0 + e1;
#pragma unroll
    for (int o = 16; o > 0; o >>= 1) sm += __shfl_xor_sync(0xffffffffu, sm, o);
    if (lane == 0) s_red2[warp] = sm;
    __syncthreads();
    float bsum = s_red2[0];
#pragma unroll
    for (int i = 1; i < 8; i++) bsum += s_red2[i];
    const float inv = 1.0f / bsum;

    const float a0 = e0 * inv;
    const float a1 = e1 * inv;
    float* arow = g_attn + (size_t)(h * 512 + l) * 512;
    arow[tid] = a0;
    arow[tid + 256] = a1;
    if (attn_out) {
        float* orow = attn_out + (size_t)(h * 512 + l) * 512;
        orow[tid] = a0;
        orow[tid + 256] = a1;
    }
}

// ---------------- kernel 4: rel context base: g_ctx = attn ⊗ rel_v ---------
// one block per (l, h); 256 thr: 8 m-groups x 32 float2-d lanes
__global__ void __launch_bounds__(256) rctx_kernel(const float* __restrict__ rel_v) {
    const int l = blockIdx.x;
    const int h = blockIdx.y;
    const int tid = threadIdx.x;
    const int d2 = tid & 31;
    const int mg = tid >> 5;

    __shared__ float  s_a[512];
    __shared__ float2 s_p[256];

    const float* arow = g_attn + (size_t)(h * 512 + l) * 512;
    s_a[tid] = arow[tid];
    s_a[tid + 256] = arow[tid + 256];
    __syncthreads();

    const float2* rv = (const float2*)(rel_v + ((size_t)(h * 512 + l) * 512) * 64);

    float2 acc = make_float2(0.f, 0.f);
#pragma unroll 4
    for (int m = mg; m < 512; m += 16) {
        float a0 = s_a[m];
        float a1 = s_a[m + 8];
        float2 r0 = rv[(size_t)m * 32 + d2];
        float2 r1 = rv[(size_t)(m + 8) * 32 + d2];
        acc.x += a0 * r0.x + a1 * r1.x;
        acc.y += a0 * r0.y + a1 * r1.y;
    }
    s_p[tid] = acc;
    __syncthreads();
    if (tid < 32) {
        float2 r = s_p[tid];
#pragma unroll
        for (int g = 1; g < 8; g++) {
            float2 t = s_p[tid + g * 32];
            r.x += t.x; r.y += t.y;
        }
        *(float2*)(g_ctx + l * 512 + h * 64 + tid * 2) = r;
    }
}

// ---------------- kernel 5: g_ctx += attn @ v (split-K atomics) ------------
// grid (8 ltile, 4 ksplit, 8 head)
__global__ void __launch_bounds__(256) av_gemm_kernel() {
    __shared__ float As[16][64];
    __shared__ float Bs[16][68];
    const int tid = threadIdx.x;
    const int h = blockIdx.z;
    const int bm = blockIdx.x * 64;       // l tile
    const int kbase = blockIdx.y * 128;   // k split
    const int tr = (tid / 16) * 4;
    const int tc = (tid % 16) * 4;
    float acc[4][4] = {};

    const int am = tid >> 2;
    const int ak = (tid & 3) * 4;
    const int bk = tid >> 4;
    const int bn4 = (tid & 15) * 4;

    const float* A = g_attn + (size_t)(h * 512) * 512;   // [l, m]
    const float* B = g_v + h * 64;                        // [m, d] stride 512

    for (int k0 = kbase; k0 < kbase + 128; k0 += 16) {
        float4 a = *(const float4*)(A + (bm + am) * 512 + k0 + ak);
        As[ak + 0][am] = a.x; As[ak + 1][am] = a.y;
        As[ak + 2][am] = a.z; As[ak + 3][am] = a.w;
        *(float4*)&Bs[bk][bn4] = *(const float4*)(B + (k0 + bk) * 512 + bn4);
        __syncthreads();
#pragma unroll
        for (int kk = 0; kk < 16; kk++) {
            float4 ra = *(const float4*)&As[kk][tr];
            float4 rb = *(const float4*)&Bs[kk][tc];
            acc[0][0] += ra.x * rb.x; acc[0][1] += ra.x * rb.y;
            acc[0][2] += ra.x * rb.z; acc[0][3] += ra.x * rb.w;
            acc[1][0] += ra.y * rb.x; acc[1][1] += ra.y * rb.y;
            acc[1][2] += ra.y * rb.z; acc[1][3] += ra.y * rb.w;
            acc[2][0] += ra.z * rb.x; acc[2][1] += ra.z * rb.y;
            acc[2][2] += ra.z * rb.z; acc[2][3] += ra.z * rb.w;
            acc[3][0] += ra.w * rb.x; acc[3][1] += ra.w * rb.y;
            acc[3][2] += ra.w * rb.z; acc[3][3] += ra.w * rb.w;
        }
        __syncthreads();
    }
#pragma unroll
    for (int i = 0; i < 4; i++)
#pragma unroll
        for (int j = 0; j < 4; j++)
            atomicAdd(&g_ctx[(bm + tr + i) * 512 + h * 64 + tc + j], acc[i][j]);
}

// ---------------- kernel 6: out = bias-init then split-K GEMM --------------
__global__ void __launch_bounds__(256) out_init_kernel(
    const float* __restrict__ bo, float* __restrict__ out) {
    int idx = blockIdx.x * 256 + threadIdx.x;
    out[idx] = bo[idx & 511];
}

// grid (8 ntile, 8 mtile, 4 ksplit)
__global__ void __launch_bounds__(256) out_gemm_kernel(
    const float* __restrict__ Wo, float* __restrict__ out) {
    __shared__ float As[16][64];
    __shared__ float Bs[16][68];
    const int tid = threadIdx.x;
    const int bm = blockIdx.y * 64;
    const int bn = blockIdx.x * 64;
    const int kbase = blockIdx.z * 128;
    const int tr = (tid / 16) * 4;
    const int tc = (tid % 16) * 4;
    float acc[4][4] = {};

    const int am = tid >> 2;
    const int ak = (tid & 3) * 4;
    const int bk = tid >> 4;
    const int bn4 = (tid & 15) * 4;

    for (int k0 = kbase; k0 < kbase + 128; k0 += 16) {
        float4 a = *(const float4*)(g_ctx + (bm + am) * 512 + k0 + ak);
        As[ak + 0][am] = a.x; As[ak + 1][am] = a.y;
        As[ak + 2][am] = a.z; As[ak + 3][am] = a.w;
        *(float4*)&Bs[bk][bn4] = *(const float4*)(Wo + (k0 + bk) * 512 + bn + bn4);
        __syncthreads();
#pragma unroll
        for (int kk = 0; kk < 16; kk++) {
            float4 ra = *(const float4*)&As[kk][tr];
            float4 rb = *(const float4*)&Bs[kk][tc];
            acc[0][0] += ra.x * rb.x; acc[0][1] += ra.x * rb.y;
            acc[0][2] += ra.x * rb.z; acc[0][3] += ra.x * rb.w;
            acc[1][0] += ra.y * rb.x; acc[1][1] += ra.y * rb.y;
            acc[1][2] += ra.y * rb.z; acc[1][3] += ra.y * rb.w;
            acc[2][0] += ra.z * rb.x; acc[2][1] += ra.z * rb.y;
            acc[2][2] += ra.z * rb.z; acc[2][3] += ra.z * rb.w;
            acc[3][0] += ra.w * rb.x; acc[3][1] += ra.w * rb.y;
            acc[3][2] += ra.w * rb.z; acc[3][3] += ra.w * rb.w;
        }
        __syncthreads();
    }
#pragma unroll
    for (int i = 0; i < 4; i++)
#pragma unroll
        for (int j = 0; j < 4; j++)
            atomicAdd(&out[(bm + tr + i) * 512 + bn + tc + j], acc[i][j]);
}

// ---------------- launch ---------------------------------------------------
extern "C" void kernel_launch(void* const* d_in, const int* in_sizes, int n_in,
                              void* d_out, int out_size) {
    const float* query = (const float*)d_in[0];
    const float* key   = (const float*)d_in[1];
    const float* value = (const float*)d_in[2];
    const float* rel_k = (const float*)d_in[3];
    const float* rel_v = (const float*)d_in[4];
    const float* Wq = (const float*)d_in[5];
    const float* bq = (const float*)d_in[6];
    const float* Wk = (const float*)d_in[7];
    const float* bk = (const float*)d_in[8];
    const float* Wv = (const float*)d_in[9];
    const float* bv = (const float*)d_in[10];
    const float* Wo = (const float*)d_in[11];
    const float* bo = (const float*)d_in[12];

    float* out = (float*)d_out;
    float* attn_out = nullptr;
    const int OUT_ELEMS = 512 * 512;
    const int ATTN_ELEMS = 8 * 512 * 512;
    if (out_size >= OUT_ELEMS + ATTN_ELEMS) attn_out = out + OUT_ELEMS;

    out_init_kernel<<<OUT_ELEMS / 256, 256>>>(bo, out);

    dim3 proj_grid(8, 8, 3);
    proj_kernel<<<proj_grid, 256>>>(query, key, value, Wq, bq, Wk, bk, Wv, bv);

    dim3 qkg(8, 8, 8);
    qk_gemm_kernel<<<qkg, 256>>>();

    dim3 lg(512, 8);
    logits_softmax_kernel<<<lg, 256>>>(rel_k, attn_out);
    rctx_kernel<<<lg, 256>>>(rel_v);

    dim3 avg(8, 4, 8);
    av_gemm_kernel<<<avg, 256>>>();

    dim3 og(8, 8, 4);
    out_gemm_kernel<<<og, 256>>>(Wo, out);
}